// round 1
// baseline (speedup 1.0000x reference)
#include <cuda_runtime.h>
#include <math.h>

// Problem constants (fixed by setup_inputs)
#define N_NODES 32768
#define E_EDGES 524288
#define F_IN    128
#define D1      256
#define D2      128
#define NT      3
#define SEQ     16
#define NNG     512   // nodes per graph
// batch = 4, N = 4*16*512

// ---------------- scratch (device globals; no allocation allowed) ----------------
__device__ float g_xn [N_NODES * F_IN];   // 16 MB normalized x
__device__ float g_h1 [N_NODES * D1];     // 32 MB
__device__ float g_h1r[N_NODES * D1];     // 32 MB
__device__ float g_h2 [N_NODES * D2];     // 16 MB
__device__ float g_deg[NT * N_NODES];
__device__ float g_dis[NT * N_NODES];
__device__ int   g_counts[N_NODES];
__device__ int   g_rowptr[N_NODES + 1];
__device__ int   g_cursor[N_NODES];
__device__ int   g_ssrc[E_EDGES];         // 2 MB  (edge src sorted by dst)
__device__ float g_sw  [NT * E_EDGES];    // 6 MB  (normalized edge weight per type, sorted)
__device__ float g_colsum[F_IN];
__device__ float g_colsq [F_IN];
__device__ float g_mean[F_IN];
__device__ float g_rstd[F_IN];

// ---------------- small prep kernels ----------------
__global__ void zero_kernel() {
    int i = blockIdx.x * 256 + threadIdx.x;            // grid 384*256 = 98304
    if (i < N_NODES)      g_counts[i] = 0;
    if (i < NT * N_NODES) g_deg[i] = 0.0f;
    if (i < F_IN) { g_colsum[i] = 0.0f; g_colsq[i] = 0.0f; }
}

// column sums / sums of squares: block = 128 threads (one per column), 256 rows per block
__global__ void stats_kernel(const float* __restrict__ x) {
    int c  = threadIdx.x;
    int r0 = blockIdx.x * 256;
    float s = 0.0f, q = 0.0f;
    for (int r = 0; r < 256; r++) {
        float v = x[(r0 + r) * F_IN + c];
        s += v; q += v * v;
    }
    atomicAdd(&g_colsum[c], s);
    atomicAdd(&g_colsq[c],  q);
}

__global__ void finstats_kernel() {
    int c = threadIdx.x;
    float n = (float)N_NODES;
    float mean = g_colsum[c] / n;
    float var  = (g_colsq[c] - n * mean * mean) / (n - 1.0f);  // ddof=1
    g_mean[c] = mean;
    g_rstd[c] = rsqrtf(var);
}

__global__ void normalize_kernel(const float* __restrict__ x) {
    int i  = blockIdx.x * 256 + threadIdx.x;  // float4 index, 1,048,576 total
    int c4 = (i & 31) * 4;                    // 32 float4 per row
    float4 v = ((const float4*)x)[i];
    v.x = (v.x - g_mean[c4 + 0]) * g_rstd[c4 + 0];
    v.y = (v.y - g_mean[c4 + 1]) * g_rstd[c4 + 1];
    v.z = (v.z - g_mean[c4 + 2]) * g_rstd[c4 + 2];
    v.w = (v.w - g_mean[c4 + 3]) * g_rstd[c4 + 3];
    ((float4*)g_xn)[i] = v;
}

// histogram of dst + weighted degree per edge type
__global__ void hist_kernel(const int* __restrict__ ei, const float* __restrict__ ea) {
    int e = blockIdx.x * 256 + threadIdx.x;
    if (e >= E_EDGES) return;
    int dst = ei[E_EDGES + e];
    atomicAdd(&g_counts[dst], 1);
    atomicAdd(&g_deg[0 * N_NODES + dst], fabsf(ea[3 * e + 0]));
    atomicAdd(&g_deg[1 * N_NODES + dst], fabsf(ea[3 * e + 1]));
    atomicAdd(&g_deg[2 * N_NODES + dst], fabsf(ea[3 * e + 2]));
}

// single-block exclusive scan over 32768 counts (1024 threads x 32)
__global__ void scan_kernel() {
    __shared__ int sums[1024];
    int tid  = threadIdx.x;
    int base = tid * 32;
    int vals[32];
    int s = 0;
#pragma unroll
    for (int i = 0; i < 32; i++) { int v = g_counts[base + i]; vals[i] = s; s += v; }
    sums[tid] = s;
    __syncthreads();
    for (int off = 1; off < 1024; off <<= 1) {
        int v = (tid >= off) ? sums[tid - off] : 0;
        __syncthreads();
        sums[tid] += v;
        __syncthreads();
    }
    int ex = (tid > 0) ? sums[tid - 1] : 0;
#pragma unroll
    for (int i = 0; i < 32; i++) {
        int p = ex + vals[i];
        g_rowptr[base + i] = p;
        g_cursor[base + i] = p;
    }
    if (tid == 1023) g_rowptr[N_NODES] = sums[1023];
}

__global__ void dis_kernel() {
    int i = blockIdx.x * 256 + threadIdx.x;
    if (i < NT * N_NODES) g_dis[i] = rsqrtf(g_deg[i] + 1.0f);
}

// scatter edges into CSR order; precompute normalized weights per type
__global__ void fill_kernel(const int* __restrict__ ei, const float* __restrict__ ea) {
    int e = blockIdx.x * 256 + threadIdx.x;
    if (e >= E_EDGES) return;
    int src = ei[e];
    int dst = ei[E_EDGES + e];
    int pos = atomicAdd(&g_cursor[dst], 1);
    g_ssrc[pos] = src;
#pragma unroll
    for (int t = 0; t < NT; t++) {
        float w = g_dis[t * N_NODES + src] * fabsf(ea[3 * e + t]) * g_dis[t * N_NODES + dst];
        g_sw[t * E_EDGES + pos] = w;
    }
}

// ---------------- SIMT fp32 GEMM: C[M,N] = A[M,K] @ W[K,N] ----------------
// BM=128, BN=64, BK=16, 128 threads, 8x8 microtile, reg-prefetch double buffer
__global__ void __launch_bounds__(128) gemm_kernel(
    const float* __restrict__ A, const float* __restrict__ W,
    float* __restrict__ C, int M, int N, int K)
{
    __shared__ float As[16][132];   // transposed A tile, +4 pad
    __shared__ float Bs[16][64];

    const int tid = threadIdx.x;
    const int tn  = (tid & 7)  * 8;   // 0..56
    const int tm  = (tid >> 3) * 8;   // 0..120
    const int bm0 = blockIdx.y * 128;
    const int bn0 = blockIdx.x * 64;

    const int a_r = tid >> 2;         // base row for A loads (0..31)
    const int a_k = (tid & 3) * 4;    // k offset within tile
    const int b_r = tid >> 4;         // base row for B loads (0..7)
    const int b_c = (tid & 15) * 4;   // col offset

    float acc[8][8];
#pragma unroll
    for (int i = 0; i < 8; i++)
#pragma unroll
        for (int j = 0; j < 8; j++) acc[i][j] = 0.0f;

    float4 aReg[4], bReg[2];

    // prologue: load k0 = 0
#pragma unroll
    for (int i = 0; i < 4; i++)
        aReg[i] = *(const float4*)(A + (bm0 + a_r + 32 * i) * K + a_k);
#pragma unroll
    for (int i = 0; i < 2; i++)
        bReg[i] = *(const float4*)(W + (b_r + 8 * i) * N + bn0 + b_c);

#pragma unroll
    for (int i = 0; i < 4; i++) {
        int r = a_r + 32 * i;
        As[a_k + 0][r] = aReg[i].x;
        As[a_k + 1][r] = aReg[i].y;
        As[a_k + 2][r] = aReg[i].z;
        As[a_k + 3][r] = aReg[i].w;
    }
#pragma unroll
    for (int i = 0; i < 2; i++)
        *(float4*)&Bs[b_r + 8 * i][b_c] = bReg[i];
    __syncthreads();

    for (int k0 = 16;; k0 += 16) {
        bool more = (k0 < K);
        if (more) {
#pragma unroll
            for (int i = 0; i < 4; i++)
                aReg[i] = *(const float4*)(A + (bm0 + a_r + 32 * i) * K + k0 + a_k);
#pragma unroll
            for (int i = 0; i < 2; i++)
                bReg[i] = *(const float4*)(W + (k0 + b_r + 8 * i) * N + bn0 + b_c);
        }
#pragma unroll
        for (int k = 0; k < 16; k++) {
            float a[8], b[8];
            *(float4*)&a[0] = *(const float4*)&As[k][tm];
            *(float4*)&a[4] = *(const float4*)&As[k][tm + 4];
            *(float4*)&b[0] = *(const float4*)&Bs[k][tn];
            *(float4*)&b[4] = *(const float4*)&Bs[k][tn + 4];
#pragma unroll
            for (int i = 0; i < 8; i++)
#pragma unroll
                for (int j = 0; j < 8; j++)
                    acc[i][j] = fmaf(a[i], b[j], acc[i][j]);
        }
        if (!more) break;
        __syncthreads();
#pragma unroll
        for (int i = 0; i < 4; i++) {
            int r = a_r + 32 * i;
            As[a_k + 0][r] = aReg[i].x;
            As[a_k + 1][r] = aReg[i].y;
            As[a_k + 2][r] = aReg[i].z;
            As[a_k + 3][r] = aReg[i].w;
        }
#pragma unroll
        for (int i = 0; i < 2; i++)
            *(float4*)&Bs[b_r + 8 * i][b_c] = bReg[i];
        __syncthreads();
    }

#pragma unroll
    for (int i = 0; i < 8; i++) {
        float* cp = C + (bm0 + tm + i) * N + bn0 + tn;
        float4 o0 = make_float4(acc[i][0], acc[i][1], acc[i][2], acc[i][3]);
        float4 o1 = make_float4(acc[i][4], acc[i][5], acc[i][6], acc[i][7]);
        *(float4*)(cp)     = o0;
        *(float4*)(cp + 4) = o1;
    }
}

// ---------------- gather aggregation (atomic-free) ----------------
// layer 1: h1r[v] = relu( sum_e w*h1[src] + dis^2[v]*h1[v] + b1 ),  D1=256 (warp: 2 float4/lane)
__global__ void gather1_kernel(const float* __restrict__ b1t, int t) {
    int lane = threadIdx.x & 31;
    int v    = blockIdx.x * 8 + (threadIdx.x >> 5);   // 4096 blocks * 8 warps = 32768

    const float* __restrict__ sw  = g_sw  + t * E_EDGES;
    const float* __restrict__ dis = g_dis + t * N_NODES;
    const float4* __restrict__ h1 = (const float4*)g_h1;

    int beg = g_rowptr[v];
    int end = g_rowptr[v + 1];

    float4 a0 = make_float4(0.f, 0.f, 0.f, 0.f);
    float4 a1 = make_float4(0.f, 0.f, 0.f, 0.f);

    for (int j = beg; j < end; j++) {
        int   src = __ldg(&g_ssrc[j]);
        float w   = __ldg(&sw[j]);
        const float4* hp = h1 + src * 64;
        float4 x0 = hp[lane];
        float4 x1 = hp[lane + 32];
        a0.x = fmaf(w, x0.x, a0.x); a0.y = fmaf(w, x0.y, a0.y);
        a0.z = fmaf(w, x0.z, a0.z); a0.w = fmaf(w, x0.w, a0.w);
        a1.x = fmaf(w, x1.x, a1.x); a1.y = fmaf(w, x1.y, a1.y);
        a1.z = fmaf(w, x1.z, a1.z); a1.w = fmaf(w, x1.w, a1.w);
    }
    float iv = dis[v]; iv = iv * iv;            // 1/(deg+1)
    const float4* hv = h1 + v * 64;
    float4 s0 = hv[lane], s1 = hv[lane + 32];
    const float4* bb = (const float4*)b1t;
    float4 b0 = bb[lane], b1v = bb[lane + 32];

    a0.x = fmaxf(fmaf(iv, s0.x, a0.x) + b0.x, 0.f);
    a0.y = fmaxf(fmaf(iv, s0.y, a0.y) + b0.y, 0.f);
    a0.z = fmaxf(fmaf(iv, s0.z, a0.z) + b0.z, 0.f);
    a0.w = fmaxf(fmaf(iv, s0.w, a0.w) + b0.w, 0.f);
    a1.x = fmaxf(fmaf(iv, s1.x, a1.x) + b1v.x, 0.f);
    a1.y = fmaxf(fmaf(iv, s1.y, a1.y) + b1v.y, 0.f);
    a1.z = fmaxf(fmaf(iv, s1.z, a1.z) + b1v.z, 0.f);
    a1.w = fmaxf(fmaf(iv, s1.w, a1.w) + b1v.w, 0.f);

    float4* o = (float4*)g_h1r + v * 64;
    o[lane]      = a0;
    o[lane + 32] = a1;
}

// layer 2: out = relu( sum w*h2[src] + dis^2*h2[v] + b2 ), D2=128, with output permutation
__global__ void gather2_kernel(const float* __restrict__ b2t, int t, float* __restrict__ out) {
    int lane = threadIdx.x & 31;
    int v    = blockIdx.x * 8 + (threadIdx.x >> 5);

    const float* __restrict__ sw  = g_sw  + t * E_EDGES;
    const float* __restrict__ dis = g_dis + t * N_NODES;
    const float4* __restrict__ h2 = (const float4*)g_h2;

    int beg = g_rowptr[v];
    int end = g_rowptr[v + 1];

    float4 a = make_float4(0.f, 0.f, 0.f, 0.f);
    for (int j = beg; j < end; j++) {
        int   src = __ldg(&g_ssrc[j]);
        float w   = __ldg(&sw[j]);
        float4 x  = h2[src * 32 + lane];
        a.x = fmaf(w, x.x, a.x); a.y = fmaf(w, x.y, a.y);
        a.z = fmaf(w, x.z, a.z); a.w = fmaf(w, x.w, a.w);
    }
    float iv = dis[v]; iv = iv * iv;
    float4 s = h2[v * 32 + lane];
    float4 b = ((const float4*)b2t)[lane];
    a.x = fmaxf(fmaf(iv, s.x, a.x) + b.x, 0.f);
    a.y = fmaxf(fmaf(iv, s.y, a.y) + b.y, 0.f);
    a.z = fmaxf(fmaf(iv, s.z, a.z) + b.z, 0.f);
    a.w = fmaxf(fmaf(iv, s.w, a.w) + b.w, 0.f);

    // node v = ((bt*SEQ + s)*NNG + vv); out[(bt*NNG+vv), s, t*D2 + d]
    int bt = v >> 13;          // / (SEQ*NNG)
    int sq = (v >> 9) & 15;    // seq position
    int vv = v & 511;          // node in graph
    int orow = bt * NNG + vv;
    int off  = (orow * SEQ + sq) * (NT * D2) + t * D2 + lane * 4;
    *(float4*)(out + off) = a;
}

// ---------------- launch ----------------
extern "C" void kernel_launch(void* const* d_in, const int* in_sizes, int n_in,
                              void* d_out, int out_size) {
    const float* x  = (const float*)d_in[0];
    const float* ea = (const float*)d_in[1];
    const float* W1 = (const float*)d_in[2];
    const float* b1 = (const float*)d_in[3];
    const float* W2 = (const float*)d_in[4];
    const float* b2 = (const float*)d_in[5];
    const int*   ei = (const int*)d_in[6];
    float* out = (float*)d_out;

    float *xn, *h1, *h1r, *h2;
    cudaGetSymbolAddress((void**)&xn,  g_xn);
    cudaGetSymbolAddress((void**)&h1,  g_h1);
    cudaGetSymbolAddress((void**)&h1r, g_h1r);
    cudaGetSymbolAddress((void**)&h2,  g_h2);

    zero_kernel     <<<384, 256>>>();
    stats_kernel    <<<128, 128>>>(x);
    finstats_kernel <<<1, 128>>>();
    normalize_kernel<<<4096, 256>>>(x);
    hist_kernel     <<<E_EDGES / 256, 256>>>(ei, ea);
    scan_kernel     <<<1, 1024>>>();
    dis_kernel      <<<384, 256>>>();
    fill_kernel     <<<E_EDGES / 256, 256>>>(ei, ea);

    for (int t = 0; t < NT; t++) {
        gemm_kernel<<<dim3(D1 / 64, N_NODES / 128), 128>>>(
            xn, W1 + t * F_IN * D1, h1, N_NODES, D1, F_IN);
        gather1_kernel<<<N_NODES / 8, 256>>>(b1 + t * D1, t);
        gemm_kernel<<<dim3(D2 / 64, N_NODES / 128), 128>>>(
            h1r, W2 + t * D1 * D2, h2, N_NODES, D2, D1);
        gather2_kernel<<<N_NODES / 8, 256>>>(b2 + t * D2, t, out);
    }
}

// round 2
// speedup vs baseline: 1.3142x; 1.3142x over previous
#include <cuda_runtime.h>
#include <math.h>

// Problem constants (fixed by setup_inputs)
#define N_NODES 32768
#define E_EDGES 524288
#define F_IN    128
#define D1      256
#define D2      128
#define NT      3
#define SEQ     16
#define NNG     512   // nodes per graph

// ---------------- scratch (device globals; no allocation allowed) ----------------
__device__ float  g_xn  [N_NODES * F_IN];            // 16 MB normalized x
__device__ float  g_agg [NT * N_NODES * F_IN];       // 48 MB aggregated xn per type
__device__ float  g_h1r [NT * N_NODES * D1];         // 96 MB relu(agg@W1+b1) per type
__device__ float  g_h2  [NT * N_NODES * D2];         // 48 MB h1r@W2 per type
__device__ float  g_deg [NT * N_NODES];
__device__ float  g_dis [NT * N_NODES];
__device__ int    g_counts[N_NODES];
__device__ int    g_rowptr[N_NODES + 1];
__device__ int    g_cursor[N_NODES];
__device__ float4 g_meta[E_EDGES];                   // 8 MB {w0,w1,w2,src-as-float} CSR by dst
__device__ float  g_colsum[F_IN];
__device__ float  g_colsq [F_IN];
__device__ float  g_mean[F_IN];
__device__ float  g_rstd[F_IN];

// ---------------- f32x2 packed-FMA helpers ----------------
__device__ __forceinline__ unsigned long long pack2(float x) {
    unsigned long long r;
    asm("mov.b64 %0, {%1, %1};" : "=l"(r) : "r"(__float_as_uint(x)));
    return r;
}
__device__ __forceinline__ void ffma2(unsigned long long& acc,
                                      unsigned long long a, unsigned long long b) {
    asm("fma.rn.f32x2 %0, %1, %2, %0;" : "+l"(acc) : "l"(a), "l"(b));
}
__device__ __forceinline__ float2 unpack2(unsigned long long v) {
    unsigned lo, hi;
    asm("mov.b64 {%0, %1}, %2;" : "=r"(lo), "=r"(hi) : "l"(v));
    return make_float2(__uint_as_float(lo), __uint_as_float(hi));
}

// ---------------- small prep kernels ----------------
__global__ void zero_kernel() {
    int i = blockIdx.x * 256 + threadIdx.x;            // grid 384*256 = 98304
    if (i < N_NODES)      g_counts[i] = 0;
    if (i < NT * N_NODES) g_deg[i] = 0.0f;
    if (i < F_IN) { g_colsum[i] = 0.0f; g_colsq[i] = 0.0f; }
}

__global__ void stats_kernel(const float* __restrict__ x) {
    int c  = threadIdx.x;
    int r0 = blockIdx.x * 256;
    float s = 0.0f, q = 0.0f;
    for (int r = 0; r < 256; r++) {
        float v = x[(r0 + r) * F_IN + c];
        s += v; q += v * v;
    }
    atomicAdd(&g_colsum[c], s);
    atomicAdd(&g_colsq[c],  q);
}

__global__ void finstats_kernel() {
    int c = threadIdx.x;
    float n = (float)N_NODES;
    float mean = g_colsum[c] / n;
    float var  = (g_colsq[c] - n * mean * mean) / (n - 1.0f);  // ddof=1
    g_mean[c] = mean;
    g_rstd[c] = rsqrtf(var);
}

__global__ void normalize_kernel(const float* __restrict__ x) {
    int i  = blockIdx.x * 256 + threadIdx.x;  // float4 index
    int c4 = (i & 31) * 4;
    float4 v = ((const float4*)x)[i];
    v.x = (v.x - g_mean[c4 + 0]) * g_rstd[c4 + 0];
    v.y = (v.y - g_mean[c4 + 1]) * g_rstd[c4 + 1];
    v.z = (v.z - g_mean[c4 + 2]) * g_rstd[c4 + 2];
    v.w = (v.w - g_mean[c4 + 3]) * g_rstd[c4 + 3];
    ((float4*)g_xn)[i] = v;
}

__global__ void hist_kernel(const int* __restrict__ ei, const float* __restrict__ ea) {
    int e = blockIdx.x * 256 + threadIdx.x;
    if (e >= E_EDGES) return;
    int dst = ei[E_EDGES + e];
    atomicAdd(&g_counts[dst], 1);
    atomicAdd(&g_deg[0 * N_NODES + dst], fabsf(ea[3 * e + 0]));
    atomicAdd(&g_deg[1 * N_NODES + dst], fabsf(ea[3 * e + 1]));
    atomicAdd(&g_deg[2 * N_NODES + dst], fabsf(ea[3 * e + 2]));
}

__global__ void scan_kernel() {
    __shared__ int sums[1024];
    int tid  = threadIdx.x;
    int base = tid * 32;
    int vals[32];
    int s = 0;
#pragma unroll
    for (int i = 0; i < 32; i++) { int v = g_counts[base + i]; vals[i] = s; s += v; }
    sums[tid] = s;
    __syncthreads();
    for (int off = 1; off < 1024; off <<= 1) {
        int v = (tid >= off) ? sums[tid - off] : 0;
        __syncthreads();
        sums[tid] += v;
        __syncthreads();
    }
    int ex = (tid > 0) ? sums[tid - 1] : 0;
#pragma unroll
    for (int i = 0; i < 32; i++) {
        int p = ex + vals[i];
        g_rowptr[base + i] = p;
        g_cursor[base + i] = p;
    }
    if (tid == 1023) g_rowptr[N_NODES] = sums[1023];
}

__global__ void dis_kernel() {
    int i = blockIdx.x * 256 + threadIdx.x;
    if (i < NT * N_NODES) g_dis[i] = rsqrtf(g_deg[i] + 1.0f);
}

// scatter edges into CSR order; pack per-edge {normalized w0,w1,w2, src}
__global__ void fill_kernel(const int* __restrict__ ei, const float* __restrict__ ea) {
    int e = blockIdx.x * 256 + threadIdx.x;
    if (e >= E_EDGES) return;
    int src = ei[e];
    int dst = ei[E_EDGES + e];
    int pos = atomicAdd(&g_cursor[dst], 1);
    float4 m;
    m.x = g_dis[0 * N_NODES + src] * fabsf(ea[3 * e + 0]) * g_dis[0 * N_NODES + dst];
    m.y = g_dis[1 * N_NODES + src] * fabsf(ea[3 * e + 1]) * g_dis[1 * N_NODES + dst];
    m.z = g_dis[2 * N_NODES + src] * fabsf(ea[3 * e + 2]) * g_dis[2 * N_NODES + dst];
    m.w = __int_as_float(src);
    g_meta[pos] = m;
}

// ---------------- fused 3-type aggregation of xn (gather, atomic-free) ----------------
// agg_t[v] = sum_e w_t * xn[src] + (1/deg_t[v]) * xn[v],  128 dims, warp per node
__global__ void gather0_kernel() {
    int lane = threadIdx.x & 31;
    int v    = blockIdx.x * 8 + (threadIdx.x >> 5);   // 4096 blocks * 8 warps

    const float4* __restrict__ xn4 = (const float4*)g_xn;
    int beg = g_rowptr[v];
    int end = g_rowptr[v + 1];

    float4 a0 = make_float4(0.f, 0.f, 0.f, 0.f);
    float4 a1 = make_float4(0.f, 0.f, 0.f, 0.f);
    float4 a2 = make_float4(0.f, 0.f, 0.f, 0.f);

    int j = beg;
    for (; j + 1 < end; j += 2) {
        float4 mA = __ldg(&g_meta[j]);
        float4 mB = __ldg(&g_meta[j + 1]);
        float4 xA = xn4[__float_as_int(mA.w) * 32 + lane];
        float4 xB = xn4[__float_as_int(mB.w) * 32 + lane];
        a0.x = fmaf(mA.x, xA.x, a0.x); a0.y = fmaf(mA.x, xA.y, a0.y);
        a0.z = fmaf(mA.x, xA.z, a0.z); a0.w = fmaf(mA.x, xA.w, a0.w);
        a1.x = fmaf(mA.y, xA.x, a1.x); a1.y = fmaf(mA.y, xA.y, a1.y);
        a1.z = fmaf(mA.y, xA.z, a1.z); a1.w = fmaf(mA.y, xA.w, a1.w);
        a2.x = fmaf(mA.z, xA.x, a2.x); a2.y = fmaf(mA.z, xA.y, a2.y);
        a2.z = fmaf(mA.z, xA.z, a2.z); a2.w = fmaf(mA.z, xA.w, a2.w);
        a0.x = fmaf(mB.x, xB.x, a0.x); a0.y = fmaf(mB.x, xB.y, a0.y);
        a0.z = fmaf(mB.x, xB.z, a0.z); a0.w = fmaf(mB.x, xB.w, a0.w);
        a1.x = fmaf(mB.y, xB.x, a1.x); a1.y = fmaf(mB.y, xB.y, a1.y);
        a1.z = fmaf(mB.y, xB.z, a1.z); a1.w = fmaf(mB.y, xB.w, a1.w);
        a2.x = fmaf(mB.z, xB.x, a2.x); a2.y = fmaf(mB.z, xB.y, a2.y);
        a2.z = fmaf(mB.z, xB.z, a2.z); a2.w = fmaf(mB.z, xB.w, a2.w);
    }
    if (j < end) {
        float4 m = __ldg(&g_meta[j]);
        float4 x = xn4[__float_as_int(m.w) * 32 + lane];
        a0.x = fmaf(m.x, x.x, a0.x); a0.y = fmaf(m.x, x.y, a0.y);
        a0.z = fmaf(m.x, x.z, a0.z); a0.w = fmaf(m.x, x.w, a0.w);
        a1.x = fmaf(m.y, x.x, a1.x); a1.y = fmaf(m.y, x.y, a1.y);
        a1.z = fmaf(m.y, x.z, a1.z); a1.w = fmaf(m.y, x.w, a1.w);
        a2.x = fmaf(m.z, x.x, a2.x); a2.y = fmaf(m.z, x.y, a2.y);
        a2.z = fmaf(m.z, x.z, a2.z); a2.w = fmaf(m.z, x.w, a2.w);
    }

    float4 xv = xn4[v * 32 + lane];
    float i0 = g_dis[0 * N_NODES + v]; i0 *= i0;
    float i1 = g_dis[1 * N_NODES + v]; i1 *= i1;
    float i2 = g_dis[2 * N_NODES + v]; i2 *= i2;
    a0.x = fmaf(i0, xv.x, a0.x); a0.y = fmaf(i0, xv.y, a0.y);
    a0.z = fmaf(i0, xv.z, a0.z); a0.w = fmaf(i0, xv.w, a0.w);
    a1.x = fmaf(i1, xv.x, a1.x); a1.y = fmaf(i1, xv.y, a1.y);
    a1.z = fmaf(i1, xv.z, a1.z); a1.w = fmaf(i1, xv.w, a1.w);
    a2.x = fmaf(i2, xv.x, a2.x); a2.y = fmaf(i2, xv.y, a2.y);
    a2.z = fmaf(i2, xv.z, a2.z); a2.w = fmaf(i2, xv.w, a2.w);

    float4* o = (float4*)g_agg;
    o[(0 * N_NODES + v) * 32 + lane] = a0;
    o[(1 * N_NODES + v) * 32 + lane] = a1;
    o[(2 * N_NODES + v) * 32 + lane] = a2;
}

// ---------------- f32x2 GEMM: C[M,N] = A[M,K] @ W[K,N] (+bias, relu) ----------------
// BM=128, BN=128, BK=16, 256 threads, 8x8 microtile as 8x4 packed u64 accumulators
__global__ void __launch_bounds__(256, 2) gemm_f32x2(
    const float* __restrict__ Abase, long long Astride,
    const float* __restrict__ Wbase, long long Wstride,
    float* __restrict__ Cbase, long long Cstride,
    const float* __restrict__ biasBase, int biasStride,
    int M, int N, int K, int doRelu)
{
    __shared__ float As[16][132];   // transposed A tile, +4 pad (row stride 528B = 33*16B)
    __shared__ float Bs[16][128];

    const int t   = blockIdx.z;
    const float* A = Abase + (long long)t * Astride;
    const float* W = Wbase + (long long)t * Wstride;
    float*       C = Cbase + (long long)t * Cstride;

    const int tid = threadIdx.x;
    const int tm  = (tid >> 4) * 8;     // 0..120
    const int tn  = (tid & 15) * 8;     // 0..120
    const int bm0 = blockIdx.y * 128;
    const int bn0 = blockIdx.x * 128;

    const int a_r = tid >> 2;           // 0..63 (rows a_r, a_r+64)
    const int a_k = (tid & 3) * 4;
    const int b_r = tid >> 5;           // 0..7 (rows b_r, b_r+8)
    const int b_c = (tid & 31) * 4;

    unsigned long long acc[8][4];
#pragma unroll
    for (int i = 0; i < 8; i++)
#pragma unroll
        for (int j = 0; j < 4; j++) acc[i][j] = 0ULL;

    float4 aReg[2], bReg[2];

    // prologue k0 = 0
    aReg[0] = *(const float4*)(A + (long long)(bm0 + a_r)      * K + a_k);
    aReg[1] = *(const float4*)(A + (long long)(bm0 + a_r + 64) * K + a_k);
    bReg[0] = *(const float4*)(W + (long long)(b_r)     * N + bn0 + b_c);
    bReg[1] = *(const float4*)(W + (long long)(b_r + 8) * N + bn0 + b_c);

    As[a_k + 0][a_r] = aReg[0].x; As[a_k + 1][a_r] = aReg[0].y;
    As[a_k + 2][a_r] = aReg[0].z; As[a_k + 3][a_r] = aReg[0].w;
    As[a_k + 0][a_r + 64] = aReg[1].x; As[a_k + 1][a_r + 64] = aReg[1].y;
    As[a_k + 2][a_r + 64] = aReg[1].z; As[a_k + 3][a_r + 64] = aReg[1].w;
    *(float4*)&Bs[b_r][b_c]     = bReg[0];
    *(float4*)&Bs[b_r + 8][b_c] = bReg[1];
    __syncthreads();

    for (int k0 = 16;; k0 += 16) {
        bool more = (k0 < K);
        if (more) {
            aReg[0] = *(const float4*)(A + (long long)(bm0 + a_r)      * K + k0 + a_k);
            aReg[1] = *(const float4*)(A + (long long)(bm0 + a_r + 64) * K + k0 + a_k);
            bReg[0] = *(const float4*)(W + (long long)(k0 + b_r)     * N + bn0 + b_c);
            bReg[1] = *(const float4*)(W + (long long)(k0 + b_r + 8) * N + bn0 + b_c);
        }
#pragma unroll
        for (int k = 0; k < 16; k++) {
            float a[8];
            *(float4*)&a[0] = *(const float4*)&As[k][tm];
            *(float4*)&a[4] = *(const float4*)&As[k][tm + 4];
            ulonglong2 t0 = *(const ulonglong2*)&Bs[k][tn];
            ulonglong2 t1 = *(const ulonglong2*)&Bs[k][tn + 4];
            unsigned long long b[4] = {t0.x, t0.y, t1.x, t1.y};
#pragma unroll
            for (int i = 0; i < 8; i++) {
                unsigned long long ap = pack2(a[i]);
                ffma2(acc[i][0], ap, b[0]);
                ffma2(acc[i][1], ap, b[1]);
                ffma2(acc[i][2], ap, b[2]);
                ffma2(acc[i][3], ap, b[3]);
            }
        }
        if (!more) break;
        __syncthreads();
        As[a_k + 0][a_r] = aReg[0].x; As[a_k + 1][a_r] = aReg[0].y;
        As[a_k + 2][a_r] = aReg[0].z; As[a_k + 3][a_r] = aReg[0].w;
        As[a_k + 0][a_r + 64] = aReg[1].x; As[a_k + 1][a_r + 64] = aReg[1].y;
        As[a_k + 2][a_r + 64] = aReg[1].z; As[a_k + 3][a_r + 64] = aReg[1].w;
        *(float4*)&Bs[b_r][b_c]     = bReg[0];
        *(float4*)&Bs[b_r + 8][b_c] = bReg[1];
        __syncthreads();
    }

    float bias[8];
    if (biasBase) {
        const float* bp = biasBase + (long long)t * biasStride + bn0 + tn;
        *(float4*)&bias[0] = *(const float4*)(bp);
        *(float4*)&bias[4] = *(const float4*)(bp + 4);
    } else {
#pragma unroll
        for (int j = 0; j < 8; j++) bias[j] = 0.0f;
    }

#pragma unroll
    for (int i = 0; i < 8; i++) {
        float o[8];
#pragma unroll
        for (int j = 0; j < 4; j++) {
            float2 p = unpack2(acc[i][j]);
            o[2 * j]     = p.x + bias[2 * j];
            o[2 * j + 1] = p.y + bias[2 * j + 1];
        }
        if (doRelu) {
#pragma unroll
            for (int j = 0; j < 8; j++) o[j] = fmaxf(o[j], 0.0f);
        }
        float* cp = C + (long long)(bm0 + tm + i) * N + bn0 + tn;
        *(float4*)(cp)     = *(float4*)&o[0];
        *(float4*)(cp + 4) = *(float4*)&o[4];
    }
}

// ---------------- layer-2 gather (per type via blockIdx.z) + output permutation ----------------
__global__ void gather2_kernel(const float* __restrict__ b2, float* __restrict__ out) {
    int lane = threadIdx.x & 31;
    int v    = blockIdx.x * 8 + (threadIdx.x >> 5);
    int tt   = blockIdx.z;

    const float4* __restrict__ h2 = (const float4*)(g_h2 + (long long)tt * N_NODES * D2);
    int beg = g_rowptr[v];
    int end = g_rowptr[v + 1];

    float4 a = make_float4(0.f, 0.f, 0.f, 0.f);
    int j = beg;
    for (; j + 1 < end; j += 2) {
        float4 mA = __ldg(&g_meta[j]);
        float4 mB = __ldg(&g_meta[j + 1]);
        float wA = (tt == 0) ? mA.x : (tt == 1) ? mA.y : mA.z;
        float wB = (tt == 0) ? mB.x : (tt == 1) ? mB.y : mB.z;
        float4 xA = h2[__float_as_int(mA.w) * 32 + lane];
        float4 xB = h2[__float_as_int(mB.w) * 32 + lane];
        a.x = fmaf(wA, xA.x, a.x); a.y = fmaf(wA, xA.y, a.y);
        a.z = fmaf(wA, xA.z, a.z); a.w = fmaf(wA, xA.w, a.w);
        a.x = fmaf(wB, xB.x, a.x); a.y = fmaf(wB, xB.y, a.y);
        a.z = fmaf(wB, xB.z, a.z); a.w = fmaf(wB, xB.w, a.w);
    }
    if (j < end) {
        float4 m = __ldg(&g_meta[j]);
        float w = (tt == 0) ? m.x : (tt == 1) ? m.y : m.z;
        float4 x = h2[__float_as_int(m.w) * 32 + lane];
        a.x = fmaf(w, x.x, a.x); a.y = fmaf(w, x.y, a.y);
        a.z = fmaf(w, x.z, a.z); a.w = fmaf(w, x.w, a.w);
    }

    float iv = g_dis[tt * N_NODES + v]; iv *= iv;
    float4 s = h2[v * 32 + lane];
    float4 b = ((const float4*)(b2 + tt * D2))[lane];
    a.x = fmaxf(fmaf(iv, s.x, a.x) + b.x, 0.f);
    a.y = fmaxf(fmaf(iv, s.y, a.y) + b.y, 0.f);
    a.z = fmaxf(fmaf(iv, s.z, a.z) + b.z, 0.f);
    a.w = fmaxf(fmaf(iv, s.w, a.w) + b.w, 0.f);

    // node v = ((bt*SEQ + sq)*NNG + vv) -> out[(bt*NNG+vv), sq, tt*D2 + d]
    int bt = v >> 13;
    int sq = (v >> 9) & 15;
    int vv = v & 511;
    int orow = bt * NNG + vv;
    long long off = ((long long)(orow * SEQ + sq)) * (NT * D2) + tt * D2 + lane * 4;
    *(float4*)(out + off) = a;
}

// ---------------- launch ----------------
extern "C" void kernel_launch(void* const* d_in, const int* in_sizes, int n_in,
                              void* d_out, int out_size) {
    const float* x  = (const float*)d_in[0];
    const float* ea = (const float*)d_in[1];
    const float* W1 = (const float*)d_in[2];
    const float* b1 = (const float*)d_in[3];
    const float* W2 = (const float*)d_in[4];
    const float* b2 = (const float*)d_in[5];
    const int*   ei = (const int*)d_in[6];
    float* out = (float*)d_out;

    float *agg, *h1r, *h2;
    cudaGetSymbolAddress((void**)&agg, g_agg);
    cudaGetSymbolAddress((void**)&h1r, g_h1r);
    cudaGetSymbolAddress((void**)&h2,  g_h2);

    zero_kernel     <<<384, 256>>>();
    stats_kernel    <<<128, 128>>>(x);
    finstats_kernel <<<1, 128>>>();
    normalize_kernel<<<4096, 256>>>(x);
    hist_kernel     <<<E_EDGES / 256, 256>>>(ei, ea);
    scan_kernel     <<<1, 1024>>>();
    dis_kernel      <<<384, 256>>>();
    fill_kernel     <<<E_EDGES / 256, 256>>>(ei, ea);
    gather0_kernel  <<<N_NODES / 8, 256>>>();

    // h1r_t = relu(agg_t @ W1_t + b1_t)   [32768,128]@[128,256], all 3 types in z
    gemm_f32x2<<<dim3(D1 / 128, N_NODES / 128, NT), 256>>>(
        agg, (long long)N_NODES * F_IN, W1, (long long)F_IN * D1,
        h1r, (long long)N_NODES * D1, b1, D1,
        N_NODES, D1, F_IN, 1);

    // h2_t = h1r_t @ W2_t   [32768,256]@[256,128]
    gemm_f32x2<<<dim3(D2 / 128, N_NODES / 128, NT), 256>>>(
        h1r, (long long)N_NODES * D1, W2, (long long)D1 * D2,
        h2, (long long)N_NODES * D2, (const float*)nullptr, 0,
        N_NODES, D2, D1, 0);

    gather2_kernel<<<dim3(N_NODES / 8, 1, NT), 256>>>(b2, out);
}